// round 14
// baseline (speedup 1.0000x reference)
#include <cuda_runtime.h>
#include <cuda_fp16.h>
#include <math.h>
#include <stdint.h>

// B=2048 windows, N=49, C=384, H=12, hd=32, nW=64
__device__ float  g_q [2048u*12*49*32];
__device__ float  g_k [2048u*12*49*32];
__device__ __half g_vh[2048u*12*49*32];  // v in fp16
__device__ __half g_oh[2048u*49*384];    // attn out (fp16), [B][N][C]
__device__ __half g_xh[2048u*49*384];
__device__ __half g_xl[2048u*49*384];    // x residual, x2048
__device__ __half g_wh[1152*384];
__device__ __half g_wl[1152*384];        // w residual, x2048
__device__ __half g_ph[384*384];
__device__ float  g_bt [169*12];
__device__ float  g_rpb[12*49*49];

#define LO_SCALE 2048.f
#define LO_INV   (1.f / 2048.f)

// ---------------------------------------------------------------------------
__device__ __forceinline__ uint32_t smem_u32(const void* p) {
    uint32_t a;
    asm("{ .reg .u64 t; cvta.to.shared.u64 t, %1; cvt.u32.u64 %0, t; }" : "=r"(a) : "l"(p));
    return a;
}
__device__ __forceinline__ void cp_async16(uint32_t dst, const void* src) {
    asm volatile("cp.async.cg.shared.global [%0], [%1], 16;" :: "r"(dst), "l"(src));
}
#define CP_COMMIT() asm volatile("cp.async.commit_group;" ::: "memory")
template<int N> __device__ __forceinline__ void cp_wait() {
    asm volatile("cp.async.wait_group %0;" :: "n"(N) : "memory");
}
__device__ __forceinline__ void ldsm4(uint32_t& r0, uint32_t& r1, uint32_t& r2, uint32_t& r3,
                                      uint32_t addr) {
    asm volatile("ldmatrix.sync.aligned.m8n8.x4.shared.b16 {%0,%1,%2,%3}, [%4];"
                 : "=r"(r0), "=r"(r1), "=r"(r2), "=r"(r3) : "r"(addr));
}
__device__ __forceinline__ void mma_f16(float& c0, float& c1, float& c2, float& c3,
                                        uint32_t a0, uint32_t a1, uint32_t a2, uint32_t a3,
                                        uint32_t b0, uint32_t b1) {
    asm volatile("mma.sync.aligned.m16n8k16.row.col.f32.f16.f16.f32 "
                 "{%0,%1,%2,%3}, {%4,%5,%6,%7}, {%8,%9}, {%0,%1,%2,%3};"
                 : "+f"(c0), "+f"(c1), "+f"(c2), "+f"(c3)
                 : "r"(a0), "r"(a1), "r"(a2), "r"(a3), "r"(b0), "r"(b1));
}

// ---------------------------------------------------------------------------
// fp16 hi/lo split: hi = f16(x), lo = f16((x - hi) * 2048)
// ---------------------------------------------------------------------------
__global__ void splith_kernel(const float* __restrict__ in, __half* __restrict__ hi,
                              __half* __restrict__ lo, int n4) {
    int i = blockIdx.x * 256 + threadIdx.x;
    if (i >= n4) return;
    float4 v = ((const float4*)in)[i];
    float vv[4] = {v.x, v.y, v.z, v.w};
    __half h[4], l[4];
    #pragma unroll
    for (int j = 0; j < 4; j++) {
        h[j] = __float2half_rn(vv[j]);
        if (lo) l[j] = __float2half_rn((vv[j] - __half2float(h[j])) * LO_SCALE);
    }
    ((__half2*)hi)[2*i]   = __half2{h[0], h[1]};
    ((__half2*)hi)[2*i+1] = __half2{h[2], h[3]};
    if (lo) {
        ((__half2*)lo)[2*i]   = __half2{l[0], l[1]};
        ((__half2*)lo)[2*i+1] = __half2{l[2], l[3]};
    }
}

// ---------------------------------------------------------------------------
// CPB MLP + gather
// ---------------------------------------------------------------------------
__global__ void cpb_kernel(const float* __restrict__ table, const float* __restrict__ w1,
                           const float* __restrict__ b1, const float* __restrict__ w2) {
    __shared__ float red[16];
    int t = blockIdx.x, j = threadIdx.x;
    float t0 = table[t * 2 + 0], t1 = table[t * 2 + 1];
    float h = fmaxf(fmaf(t0, w1[j * 2 + 0], fmaf(t1, w1[j * 2 + 1], b1[j])), 0.f);
    for (int hh = 0; hh < 12; hh++) {
        float v = h * w2[hh * 512 + j];
        #pragma unroll
        for (int o = 16; o > 0; o >>= 1) v += __shfl_down_sync(0xffffffffu, v, o);
        if ((j & 31) == 0) red[j >> 5] = v;
        __syncthreads();
        if (j == 0) {
            float s = 0.f;
            #pragma unroll
            for (int w = 0; w < 16; w++) s += red[w];
            g_bt[t * 12 + hh] = 16.f / (1.f + expf(-s));
        }
        __syncthreads();
    }
}
__global__ void gather_kernel(const int* __restrict__ idx) {
    int e = blockIdx.x * 256 + threadIdx.x;
    if (e >= 12 * 49 * 49) return;
    int h = e / 2401, ij = e - h * 2401;
    g_rpb[e] = g_bt[idx[ij] * 12 + h];
}

// ---------------------------------------------------------------------------
// fp16-limb warp-MMA GEMM, K-chunk 96, 2-stage single-sync cp.async pipeline.
// TERMS=3: hi*hi + (lo*hi + hi*lo)/2048 (q,k). TERMS=1: hi*hi (v fp16, proj).
// 512 thr, 16 warps 4x4, warp tile 32x32, 128x128 block tile, pitch-104 rows.
// 4 iterations, 1 __syncthreads per iteration.
// ---------------------------------------------------------------------------
#define PITCHE 104                          // fp16 elems per smem row (208B)
#define COMP_B (128 * PITCHE * 2)           // 26624 B per limb tile
#define GEMM_SMEM3 (2 * 4 * COMP_B)         // 212992
#define GEMM_SMEM1 (2 * 2 * COMP_B)         // 106496

template<int TERMS>
__global__ void __launch_bounds__(512) gemm_mma(
    const __half* __restrict__ Ahi, const __half* __restrict__ Alo,
    const __half* __restrict__ Bhi, const __half* __restrict__ Blo,
    int mode, int n_base,
    const float* __restrict__ bq, const float* __restrict__ bv,
    const float* __restrict__ bp, float* __restrict__ outp)
{
    constexpr int NCOMP = (TERMS == 3) ? 4 : 2;
    constexpr int C_AHI = 0;
    constexpr int C_ALO = 1;
    constexpr int C_BHI = (TERMS == 3) ? 2 : 1;
    constexpr int C_BLO = 3;
    constexpr uint32_t STAGE_B = NCOMP * COMP_B;

    extern __shared__ char sm[];
    uint32_t sbase = smem_u32(sm);
    int tid = threadIdx.x, wid = tid >> 5, lane = tid & 31;
    int g = lane >> 2, t = lane & 3;
    int grp = lane >> 3, rin = lane & 7;
    int m0 = blockIdx.x * 128, n0 = n_base + blockIdx.y * 128;
    int wm = (wid >> 2) * 32, wn = (wid & 3) * 32;

    float cm[2][4][4], cx[2][4][4];
    #pragma unroll
    for (int mi = 0; mi < 2; mi++)
        #pragma unroll
        for (int nj = 0; nj < 4; nj++)
            #pragma unroll
            for (int r = 0; r < 4; r++) { cm[mi][nj][r] = 0.f; cx[mi][nj][r] = 0.f; }

    uint32_t abyte[2], bbyte[2];
    #pragma unroll
    for (int mi = 0; mi < 2; mi++)
        abyte[mi] = (uint32_t)((wm + 16 * mi + (grp & 1) * 8 + rin) * (PITCHE * 2)
                               + (grp >> 1) * 16);
    #pragma unroll
    for (int j = 0; j < 2; j++)
        bbyte[j] = (uint32_t)((wn + 16 * j + (grp >> 1) * 8 + rin) * (PITCHE * 2)
                              + (grp & 1) * 16);

    // stage loader: 128 rows x 96 k fp16 per limb = 1536 x 16B per comp
    auto load_stage = [&](int it, int s) {
        int k0 = it * 96;
        uint32_t sb = sbase + (uint32_t)s * STAGE_B;
        #pragma unroll
        for (int q = 0; q < 3; q++) {
            int idx = q * 512 + tid;
            int r = idx / 12, seg = idx - r * 12;
            uint32_t off = (uint32_t)(r * (PITCHE * 2) + seg * 16);
            size_t ga = (size_t)(m0 + r) * 384 + k0 + seg * 8;
            size_t gb = (size_t)(n0 + r) * 384 + k0 + seg * 8;
            cp_async16(sb + C_AHI * COMP_B + off, Ahi + ga);
            cp_async16(sb + C_BHI * COMP_B + off, Bhi + gb);
            if (TERMS == 3) {
                cp_async16(sb + C_ALO * COMP_B + off, Alo + ga);
                cp_async16(sb + C_BLO * COMP_B + off, Blo + gb);
            }
        }
        CP_COMMIT();
    };

    load_stage(0, 0);

    for (int it = 0; it < 4; ++it) {
        int s = it & 1;
        cp_wait<0>();
        __syncthreads();   // stage it visible to all; slot (it+1)&1 provably free
        if (it + 1 < 4) load_stage(it + 1, (it + 1) & 1);
        uint32_t sb = sbase + (uint32_t)s * STAGE_B;
        #pragma unroll
        for (int kc = 0; kc < 6; kc++) {
            uint32_t kb = (uint32_t)(kc * 32);
            uint32_t ah[2][4], al[2][4], bh[2][4], bl[2][4];
            #pragma unroll
            for (int mi = 0; mi < 2; mi++) {
                uint32_t ao = sb + abyte[mi] + kb;
                ldsm4(ah[mi][0], ah[mi][1], ah[mi][2], ah[mi][3], ao + C_AHI * COMP_B);
                if (TERMS == 3)
                    ldsm4(al[mi][0], al[mi][1], al[mi][2], al[mi][3], ao + C_ALO * COMP_B);
            }
            #pragma unroll
            for (int j = 0; j < 2; j++) {
                uint32_t bo = sb + bbyte[j] + kb;
                ldsm4(bh[j][0], bh[j][1], bh[j][2], bh[j][3], bo + C_BHI * COMP_B);
                if (TERMS == 3)
                    ldsm4(bl[j][0], bl[j][1], bl[j][2], bl[j][3], bo + C_BLO * COMP_B);
            }
            #pragma unroll
            for (int mi = 0; mi < 2; mi++)
                #pragma unroll
                for (int nj = 0; nj < 4; nj++) {
                    int j = nj >> 1, hf = (nj & 1) * 2;
                    mma_f16(cm[mi][nj][0], cm[mi][nj][1], cm[mi][nj][2], cm[mi][nj][3],
                            ah[mi][0], ah[mi][1], ah[mi][2], ah[mi][3],
                            bh[j][hf], bh[j][hf + 1]);
                }
            if (TERMS == 3) {
                #pragma unroll
                for (int mi = 0; mi < 2; mi++)
                    #pragma unroll
                    for (int nj = 0; nj < 4; nj++) {
                        int j = nj >> 1, hf = (nj & 1) * 2;
                        mma_f16(cx[mi][nj][0], cx[mi][nj][1], cx[mi][nj][2], cx[mi][nj][3],
                                al[mi][0], al[mi][1], al[mi][2], al[mi][3],
                                bh[j][hf], bh[j][hf + 1]);
                    }
                #pragma unroll
                for (int mi = 0; mi < 2; mi++)
                    #pragma unroll
                    for (int nj = 0; nj < 4; nj++) {
                        int j = nj >> 1, hf = (nj & 1) * 2;
                        mma_f16(cx[mi][nj][0], cx[mi][nj][1], cx[mi][nj][2], cx[mi][nj][3],
                                ah[mi][0], ah[mi][1], ah[mi][2], ah[mi][3],
                                bl[j][hf], bl[j][hf + 1]);
                    }
            }
        }
    }

    #pragma unroll
    for (int mi = 0; mi < 2; mi++) {
        #pragma unroll
        for (int half = 0; half < 2; half++) {
            int row = m0 + wm + 16 * mi + g + 8 * half;
            int b = row / 49, nn = row - b * 49;
            #pragma unroll
            for (int nj = 0; nj < 4; nj++) {
                int col = n0 + wn + 8 * nj + 2 * t;
                float2 v;
                if (TERMS == 3) {
                    v.x = fmaf(cx[mi][nj][2 * half + 0], LO_INV, cm[mi][nj][2 * half + 0]);
                    v.y = fmaf(cx[mi][nj][2 * half + 1], LO_INV, cm[mi][nj][2 * half + 1]);
                } else {
                    v.x = cm[mi][nj][2 * half + 0];
                    v.y = cm[mi][nj][2 * half + 1];
                }
                if (mode == 0) {
                    int which = col / 384;
                    int rem = col - which * 384;
                    int h = rem >> 5, d = rem & 31;
                    if (TERMS == 3) {
                        if (which == 0) { v.x += bq[rem]; v.y += bq[rem + 1]; }
                        float* dst = ((which == 0) ? g_q : g_k)
                                     + (((size_t)b * 12 + h) * 49 + nn) * 32 + d;
                        *(float2*)dst = v;
                    } else {
                        v.x += bv[rem]; v.y += bv[rem + 1];
                        __half* dst = g_vh + (((size_t)b * 12 + h) * 49 + nn) * 32 + d;
                        *(__half2*)dst = __half2{__float2half_rn(v.x), __float2half_rn(v.y)};
                    }
                } else {
                    v.x += bp[col]; v.y += bp[col + 1];
                    *(float2*)(outp + (size_t)row * 384 + col) = v;
                }
            }
        }
    }
}

// ---------------------------------------------------------------------------
// Attention v3 (round-13): pitch-36 smem, 245-thr S, 200-thr PV, fp16 v in.
// ---------------------------------------------------------------------------
#define QP 36
#define SP 50

__global__ void __launch_bounds__(256) attn_kernel(const float* __restrict__ mask,
                                                   const float* __restrict__ logit_scale)
{
    __shared__ float sq[49 * QP];
    __shared__ float sk[49 * QP];
    __shared__ float sv[49 * QP];
    __shared__ float sS[49 * SP];
    __shared__ float sredA[245];
    __shared__ float sredB[245];
    int bh = blockIdx.x;
    int b = bh / 12, h = bh - b * 12;
    int tid = threadIdx.x;

    size_t base = (size_t)bh * 49 * 32;
    const float4* gq4 = (const float4*)(g_q + base);
    const float4* gk4 = (const float4*)(g_k + base);
    for (int u = tid; u < 784; u += 256) {
        if (u < 392) {
            int r = u >> 3, c4 = (u & 7) * 4;
            *(float4*)(sq + r * QP + c4) = gq4[u];
        } else {
            int w = u - 392;
            int r = w >> 3, c4 = (w & 7) * 4;
            *(float4*)(sk + r * QP + c4) = gk4[w];
        }
    }
    if (tid < 196) {
        int r = tid >> 2, c8 = (tid & 3) * 8;
        uint4 pv = *(const uint4*)(g_vh + base + r * 32 + c8);
        float2 f0 = __half22float2(*(__half2*)&pv.x);
        float2 f1 = __half22float2(*(__half2*)&pv.y);
        float2 f2 = __half22float2(*(__half2*)&pv.z);
        float2 f3 = __half22float2(*(__half2*)&pv.w);
        float* d = sv + r * QP + c8;
        d[0] = f0.x; d[1] = f0.y; d[2] = f1.x; d[3] = f1.y;
        d[4] = f2.x; d[5] = f2.y; d[6] = f3.x; d[7] = f3.y;
    }
    __syncthreads();

    if (tid < 98) {
        int r = (tid < 49) ? tid : tid - 49;
        float* s = (tid < 49) ? sq : sk;
        float ss = 0.f;
        #pragma unroll
        for (int d = 0; d < 32; d++) { float x = s[r * QP + d]; ss = fmaf(x, x, ss); }
        float inv = 1.f / fmaxf(sqrtf(ss), 1e-12f);
        if (tid < 49) inv *= expf(fminf(logit_scale[h], 4.60517018598809136804f));
        #pragma unroll
        for (int d = 0; d < 32; d++) s[r * QP + d] *= inv;
    }
    __syncthreads();

    int si = tid / 5, sp = tid - si * 5;
    int j0 = sp * 10, j1 = min(j0 + 10, 49);
    if (tid < 245) {
        float4 qr[8];
        #pragma unroll
        for (int u = 0; u < 8; u++) qr[u] = *(const float4*)(sq + si * QP + u * 4);
        for (int j = j0; j < j1; j++) {
            float a0 = 0.f;
            #pragma unroll
            for (int u = 0; u < 8; u++) {
                float4 kv = *(const float4*)(sk + j * QP + u * 4);
                a0 = fmaf(qr[u].x, kv.x, a0); a0 = fmaf(qr[u].y, kv.y, a0);
                a0 = fmaf(qr[u].z, kv.z, a0); a0 = fmaf(qr[u].w, kv.w, a0);
            }
            sS[si * SP + j] = a0;
        }
    }
    __syncthreads();

    if (tid < 245) {
        const float* rp = g_rpb + (h * 49 + si) * 49;
        const float* mp = mask + ((size_t)(b & 63) * 49 + si) * 49;
        float lmax = -1e30f;
        for (int j = j0; j < j1; j++) {
            float s = sS[si * SP + j] + rp[j] + mp[j];
            sS[si * SP + j] = s;
            lmax = fmaxf(lmax, s);
        }
        sredA[tid] = lmax;
    }
    __syncthreads();
    if (tid < 245) {
        float mx = sredA[si * 5];
        #pragma unroll
        for (int p = 1; p < 5; p++) mx = fmaxf(mx, sredA[si * 5 + p]);
        float lsum = 0.f;
        for (int j = j0; j < j1; j++) {
            float e = expf(sS[si * SP + j] - mx);
            sS[si * SP + j] = e;
            lsum += e;
        }
        sredB[tid] = lsum;
    }
    __syncthreads();
    if (tid < 245) {
        float sum = sredB[si * 5];
        #pragma unroll
        for (int p = 1; p < 5; p++) sum += sredB[si * 5 + p];
        float inv = 1.f / sum;
        for (int j = j0; j < j1; j++) sS[si * SP + j] *= inv;
    }
    __syncthreads();

    if (tid < 200) {
        int ipart = tid >> 3, dq = tid & 7;
        int r0 = ipart * 2;
        bool has1 = (r0 + 1 < 49);
        float4 a0 = {0, 0, 0, 0}, a1 = {0, 0, 0, 0};
        for (int j = 0; j < 49; j++) {
            float4 v = *(const float4*)(sv + j * QP + dq * 4);
            float s0 = sS[r0 * SP + j];
            a0.x = fmaf(s0, v.x, a0.x); a0.y = fmaf(s0, v.y, a0.y);
            a0.z = fmaf(s0, v.z, a0.z); a0.w = fmaf(s0, v.w, a0.w);
            if (has1) {
                float s1 = sS[(r0 + 1) * SP + j];
                a1.x = fmaf(s1, v.x, a1.x); a1.y = fmaf(s1, v.y, a1.y);
                a1.z = fmaf(s1, v.z, a1.z); a1.w = fmaf(s1, v.w, a1.w);
            }
        }
        size_t o0 = ((size_t)b * 49 + r0) * 384 + h * 32 + dq * 4;
        *(__half2*)(g_oh + o0)     = __half2{__float2half_rn(a0.x), __float2half_rn(a0.y)};
        *(__half2*)(g_oh + o0 + 2) = __half2{__float2half_rn(a0.z), __float2half_rn(a0.w)};
        if (has1) {
            size_t o1 = o0 + 384;
            *(__half2*)(g_oh + o1)     = __half2{__float2half_rn(a1.x), __float2half_rn(a1.y)};
            *(__half2*)(g_oh + o1 + 2) = __half2{__float2half_rn(a1.z), __float2half_rn(a1.w)};
        }
    }
}

// ---------------------------------------------------------------------------
extern "C" void kernel_launch(void* const* d_in, const int* in_sizes, int n_in,
                              void* d_out, int out_size) {
    const float* x           = (const float*)d_in[0];
    const float* mask        = (const float*)d_in[1];
    const float* qkv_w       = (const float*)d_in[2];
    const float* q_bias      = (const float*)d_in[3];
    const float* v_bias      = (const float*)d_in[4];
    const float* logit_scale = (const float*)d_in[5];
    const float* cpb_w1      = (const float*)d_in[6];
    const float* cpb_b1      = (const float*)d_in[7];
    const float* cpb_w2      = (const float*)d_in[8];
    const float* proj_w      = (const float*)d_in[9];
    const float* proj_b      = (const float*)d_in[10];
    const float* table       = (const float*)d_in[11];
    const int*   idx         = (const int*)d_in[12];
    float* out = (float*)d_out;

    cudaFuncSetAttribute(gemm_mma<3>, cudaFuncAttributeMaxDynamicSharedMemorySize, GEMM_SMEM3);
    cudaFuncSetAttribute(gemm_mma<1>, cudaFuncAttributeMaxDynamicSharedMemorySize, GEMM_SMEM1);

    __half *xh, *xl, *wh, *wl, *ph, *oh;
    cudaGetSymbolAddress((void**)&xh, g_xh);
    cudaGetSymbolAddress((void**)&xl, g_xl);
    cudaGetSymbolAddress((void**)&wh, g_wh);
    cudaGetSymbolAddress((void**)&wl, g_wl);
    cudaGetSymbolAddress((void**)&ph, g_ph);
    cudaGetSymbolAddress((void**)&oh, g_oh);

    splith_kernel<<<(2048*49*384/4 + 255)/256, 256>>>(x, xh, xl, 2048*49*384/4);
    splith_kernel<<<(1152*384/4 + 255)/256, 256>>>(qkv_w, wh, wl, 1152*384/4);
    splith_kernel<<<(384*384/4 + 255)/256, 256>>>(proj_w, ph, nullptr, 384*384/4);

    cpb_kernel<<<169, 512>>>(table, cpb_w1, cpb_b1, cpb_w2);
    gather_kernel<<<(12 * 2401 + 255) / 256, 256>>>(idx);

    // QKV: q,k columns (n 0..767) 3-term; v columns (n 768..1151) 1-term (fp16 out)
    gemm_mma<3><<<dim3(784, 6), 512, GEMM_SMEM3>>>(xh, xl, wh, wl, 0, 0,
                                                   q_bias, v_bias, nullptr, nullptr);
    gemm_mma<1><<<dim3(784, 3), 512, GEMM_SMEM1>>>(xh, nullptr, wh, nullptr, 0, 768,
                                                   q_bias, v_bias, nullptr, nullptr);
    attn_kernel<<<2048 * 12, 256>>>(mask, logit_scale);
    gemm_mma<1><<<dim3(784, 3), 512, GEMM_SMEM1>>>(oh, nullptr, ph, nullptr, 1, 0,
                                                   nullptr, nullptr, proj_b, out);
}

// round 15
// speedup vs baseline: 1.0797x; 1.0797x over previous
#include <cuda_runtime.h>
#include <cuda_fp16.h>
#include <math.h>
#include <stdint.h>

// B=2048 windows, N=49, C=384, H=12, hd=32, nW=64
__device__ float  g_q [2048u*12*49*32];
__device__ float  g_k [2048u*12*49*32];
__device__ __half g_vh[2048u*12*49*32];  // v in fp16
__device__ __half g_oh[2048u*49*384];    // attn out (fp16), [B][N][C]
__device__ __half g_xh[2048u*49*384];
__device__ __half g_xl[2048u*49*384];    // x residual, x2048
__device__ __half g_wh[1152*384];
__device__ __half g_wl[1152*384];        // w residual, x2048
__device__ __half g_ph[384*384];
__device__ float  g_bt [169*12];
__device__ float  g_rpb[12*49*49];

#define LO_SCALE 2048.f
#define LO_INV   (1.f / 2048.f)

// ---------------------------------------------------------------------------
__device__ __forceinline__ uint32_t smem_u32(const void* p) {
    uint32_t a;
    asm("{ .reg .u64 t; cvta.to.shared.u64 t, %1; cvt.u32.u64 %0, t; }" : "=r"(a) : "l"(p));
    return a;
}
__device__ __forceinline__ void cp_async16(uint32_t dst, const void* src) {
    asm volatile("cp.async.cg.shared.global [%0], [%1], 16;" :: "r"(dst), "l"(src));
}
#define CP_COMMIT() asm volatile("cp.async.commit_group;" ::: "memory")
template<int N> __device__ __forceinline__ void cp_wait() {
    asm volatile("cp.async.wait_group %0;" :: "n"(N) : "memory");
}
__device__ __forceinline__ void ldsm4(uint32_t& r0, uint32_t& r1, uint32_t& r2, uint32_t& r3,
                                      uint32_t addr) {
    asm volatile("ldmatrix.sync.aligned.m8n8.x4.shared.b16 {%0,%1,%2,%3}, [%4];"
                 : "=r"(r0), "=r"(r1), "=r"(r2), "=r"(r3) : "r"(addr));
}
__device__ __forceinline__ void mma_f16(float& c0, float& c1, float& c2, float& c3,
                                        uint32_t a0, uint32_t a1, uint32_t a2, uint32_t a3,
                                        uint32_t b0, uint32_t b1) {
    asm volatile("mma.sync.aligned.m16n8k16.row.col.f32.f16.f16.f32 "
                 "{%0,%1,%2,%3}, {%4,%5,%6,%7}, {%8,%9}, {%0,%1,%2,%3};"
                 : "+f"(c0), "+f"(c1), "+f"(c2), "+f"(c3)
                 : "r"(a0), "r"(a1), "r"(a2), "r"(a3), "r"(b0), "r"(b1));
}

// ---------------------------------------------------------------------------
// fp16 hi/lo split: hi = f16(x), lo = f16((x - hi) * 2048). 8 floats/thread.
// ---------------------------------------------------------------------------
__global__ void splith_kernel(const float* __restrict__ in, __half* __restrict__ hi,
                              __half* __restrict__ lo, int n8) {
    int i = blockIdx.x * 256 + threadIdx.x;
    if (i >= n8) return;
    float4 v0 = ((const float4*)in)[2 * i];
    float4 v1 = ((const float4*)in)[2 * i + 1];
    float vv[8] = {v0.x, v0.y, v0.z, v0.w, v1.x, v1.y, v1.z, v1.w};
    __half h[8], l[8];
    #pragma unroll
    for (int j = 0; j < 8; j++) {
        h[j] = __float2half_rn(vv[j]);
        if (lo) l[j] = __float2half_rn((vv[j] - __half2float(h[j])) * LO_SCALE);
    }
    uint4 hp;
    ((__half2*)&hp)[0] = __half2{h[0], h[1]};
    ((__half2*)&hp)[1] = __half2{h[2], h[3]};
    ((__half2*)&hp)[2] = __half2{h[4], h[5]};
    ((__half2*)&hp)[3] = __half2{h[6], h[7]};
    ((uint4*)hi)[i] = hp;
    if (lo) {
        uint4 lp;
        ((__half2*)&lp)[0] = __half2{l[0], l[1]};
        ((__half2*)&lp)[1] = __half2{l[2], l[3]};
        ((__half2*)&lp)[2] = __half2{l[4], l[5]};
        ((__half2*)&lp)[3] = __half2{l[6], l[7]};
        ((uint4*)lo)[i] = lp;
    }
}

// ---------------------------------------------------------------------------
// CPB MLP + gather
// ---------------------------------------------------------------------------
__global__ void cpb_kernel(const float* __restrict__ table, const float* __restrict__ w1,
                           const float* __restrict__ b1, const float* __restrict__ w2) {
    __shared__ float red[16];
    int t = blockIdx.x, j = threadIdx.x;
    float t0 = table[t * 2 + 0], t1 = table[t * 2 + 1];
    float h = fmaxf(fmaf(t0, w1[j * 2 + 0], fmaf(t1, w1[j * 2 + 1], b1[j])), 0.f);
    for (int hh = 0; hh < 12; hh++) {
        float v = h * w2[hh * 512 + j];
        #pragma unroll
        for (int o = 16; o > 0; o >>= 1) v += __shfl_down_sync(0xffffffffu, v, o);
        if ((j & 31) == 0) red[j >> 5] = v;
        __syncthreads();
        if (j == 0) {
            float s = 0.f;
            #pragma unroll
            for (int w = 0; w < 16; w++) s += red[w];
            g_bt[t * 12 + hh] = 16.f / (1.f + expf(-s));
        }
        __syncthreads();
    }
}
__global__ void gather_kernel(const int* __restrict__ idx) {
    int e = blockIdx.x * 256 + threadIdx.x;
    if (e >= 12 * 49 * 49) return;
    int h = e / 2401, ij = e - h * 2401;
    g_rpb[e] = g_bt[idx[ij] * 12 + h];
}

// ---------------------------------------------------------------------------
// fp16-limb warp-MMA GEMM, K-chunk 64, 3-stage single-sync cp.async pipeline.
// (round-13 configuration — best known)
// TERMS=3: hi*hi + (lo*hi + hi*lo)/2048 (q,k). TERMS=1: hi*hi (v fp16, proj).
// 512 thr, 16 warps 4x4, warp tile 32x32, 128x128 block tile, pitch-72 rows.
// ---------------------------------------------------------------------------
#define PITCHE 72
#define COMP_B (128 * PITCHE * 2)          // 18432 B per limb tile
#define GEMM_SMEM3 (3 * 4 * COMP_B)        // 221184
#define GEMM_SMEM1 (3 * 2 * COMP_B)        // 110592

template<int TERMS>
__global__ void __launch_bounds__(512) gemm_mma(
    const __half* __restrict__ Ahi, const __half* __restrict__ Alo,
    const __half* __restrict__ Bhi, const __half* __restrict__ Blo,
    int mode, int n_base,
    const float* __restrict__ bq, const float* __restrict__ bv,
    const float* __restrict__ bp, float* __restrict__ outp)
{
    constexpr int NCOMP = (TERMS == 3) ? 4 : 2;
    constexpr int C_AHI = 0;
    constexpr int C_ALO = 1;
    constexpr int C_BHI = (TERMS == 3) ? 2 : 1;
    constexpr int C_BLO = 3;
    constexpr uint32_t STAGE_B = NCOMP * COMP_B;

    extern __shared__ char sm[];
    uint32_t sbase = smem_u32(sm);
    int tid = threadIdx.x, wid = tid >> 5, lane = tid & 31;
    int g = lane >> 2, t = lane & 3;
    int grp = lane >> 3, rin = lane & 7;
    int m0 = blockIdx.x * 128, n0 = n_base + blockIdx.y * 128;
    int wm = (wid >> 2) * 32, wn = (wid & 3) * 32;

    float cm[2][4][4], cx[2][4][4];
    #pragma unroll
    for (int mi = 0; mi < 2; mi++)
        #pragma unroll
        for (int nj = 0; nj < 4; nj++)
            #pragma unroll
            for (int r = 0; r < 4; r++) { cm[mi][nj][r] = 0.f; cx[mi][nj][r] = 0.f; }

    uint32_t abyte[2], bbyte[2];
    #pragma unroll
    for (int mi = 0; mi < 2; mi++)
        abyte[mi] = (uint32_t)((wm + 16 * mi + (grp & 1) * 8 + rin) * (PITCHE * 2)
                               + (grp >> 1) * 16);
    #pragma unroll
    for (int j = 0; j < 2; j++)
        bbyte[j] = (uint32_t)((wn + 16 * j + (grp >> 1) * 8 + rin) * (PITCHE * 2)
                              + (grp & 1) * 16);

    auto load_stage = [&](int it, int s) {
        int k0 = it * 64;
        uint32_t sb = sbase + (uint32_t)s * STAGE_B;
        #pragma unroll
        for (int q = 0; q < 2; q++) {
            int cc = q * 512 + tid;
            int r = cc >> 3, seg = cc & 7;
            uint32_t off = (uint32_t)(r * (PITCHE * 2) + seg * 16);
            size_t ga = (size_t)(m0 + r) * 384 + k0 + seg * 8;
            size_t gb = (size_t)(n0 + r) * 384 + k0 + seg * 8;
            cp_async16(sb + C_AHI * COMP_B + off, Ahi + ga);
            cp_async16(sb + C_BHI * COMP_B + off, Bhi + gb);
            if (TERMS == 3) {
                cp_async16(sb + C_ALO * COMP_B + off, Alo + ga);
                cp_async16(sb + C_BLO * COMP_B + off, Blo + gb);
            }
        }
        CP_COMMIT();
    };

    load_stage(0, 0);
    load_stage(1, 1);

    for (int it = 0; it < 6; ++it) {
        int s = it % 3;
        if (it < 5) cp_wait<1>(); else cp_wait<0>();
        __syncthreads();   // stage s ready; all warps done with iter it-1 -> slot (it+2)%3 free
        if (it + 2 < 6) load_stage(it + 2, (it + 2) % 3);
        uint32_t sb = sbase + (uint32_t)s * STAGE_B;
        #pragma unroll
        for (int kc = 0; kc < 4; kc++) {
            uint32_t kb = (uint32_t)(kc * 32);
            uint32_t ah[2][4], al[2][4], bh[2][4], bl[2][4];
            #pragma unroll
            for (int mi = 0; mi < 2; mi++) {
                uint32_t ao = sb + abyte[mi] + kb;
                ldsm4(ah[mi][0], ah[mi][1], ah[mi][2], ah[mi][3], ao + C_AHI * COMP_B);
                if (TERMS == 3)
                    ldsm4(al[mi][0], al[mi][1], al[mi][2], al[mi][3], ao + C_ALO * COMP_B);
            }
            #pragma unroll
            for (int j = 0; j < 2; j++) {
                uint32_t bo = sb + bbyte[j] + kb;
                ldsm4(bh[j][0], bh[j][1], bh[j][2], bh[j][3], bo + C_BHI * COMP_B);
                if (TERMS == 3)
                    ldsm4(bl[j][0], bl[j][1], bl[j][2], bl[j][3], bo + C_BLO * COMP_B);
            }
            #pragma unroll
            for (int mi = 0; mi < 2; mi++)
                #pragma unroll
                for (int nj = 0; nj < 4; nj++) {
                    int j = nj >> 1, hf = (nj & 1) * 2;
                    mma_f16(cm[mi][nj][0], cm[mi][nj][1], cm[mi][nj][2], cm[mi][nj][3],
                            ah[mi][0], ah[mi][1], ah[mi][2], ah[mi][3],
                            bh[j][hf], bh[j][hf + 1]);
                }
            if (TERMS == 3) {
                #pragma unroll
                for (int mi = 0; mi < 2; mi++)
                    #pragma unroll
                    for (int nj = 0; nj < 4; nj++) {
                        int j = nj >> 1, hf = (nj & 1) * 2;
                        mma_f16(cx[mi][nj][0], cx[mi][nj][1], cx[mi][nj][2], cx[mi][nj][3],
                                al[mi][0], al[mi][1], al[mi][2], al[mi][3],
                                bh[j][hf], bh[j][hf + 1]);
                    }
                #pragma unroll
                for (int mi = 0; mi < 2; mi++)
                    #pragma unroll
                    for (int nj = 0; nj < 4; nj++) {
                        int j = nj >> 1, hf = (nj & 1) * 2;
                        mma_f16(cx[mi][nj][0], cx[mi][nj][1], cx[mi][nj][2], cx[mi][nj][3],
                                ah[mi][0], ah[mi][1], ah[mi][2], ah[mi][3],
                                bl[j][hf], bl[j][hf + 1]);
                    }
            }
        }
    }

    #pragma unroll
    for (int mi = 0; mi < 2; mi++) {
        #pragma unroll
        for (int half = 0; half < 2; half++) {
            int row = m0 + wm + 16 * mi + g + 8 * half;
            int b = row / 49, nn = row - b * 49;
            #pragma unroll
            for (int nj = 0; nj < 4; nj++) {
                int col = n0 + wn + 8 * nj + 2 * t;
                float2 v;
                if (TERMS == 3) {
                    v.x = fmaf(cx[mi][nj][2 * half + 0], LO_INV, cm[mi][nj][2 * half + 0]);
                    v.y = fmaf(cx[mi][nj][2 * half + 1], LO_INV, cm[mi][nj][2 * half + 1]);
                } else {
                    v.x = cm[mi][nj][2 * half + 0];
                    v.y = cm[mi][nj][2 * half + 1];
                }
                if (mode == 0) {
                    int which = col / 384;
                    int rem = col - which * 384;
                    int h = rem >> 5, d = rem & 31;
                    if (TERMS == 3) {
                        if (which == 0) { v.x += bq[rem]; v.y += bq[rem + 1]; }
                        float* dst = ((which == 0) ? g_q : g_k)
                                     + (((size_t)b * 12 + h) * 49 + nn) * 32 + d;
                        *(float2*)dst = v;
                    } else {
                        v.x += bv[rem]; v.y += bv[rem + 1];
                        __half* dst = g_vh + (((size_t)b * 12 + h) * 49 + nn) * 32 + d;
                        *(__half2*)dst = __half2{__float2half_rn(v.x), __float2half_rn(v.y)};
                    }
                } else {
                    v.x += bp[col]; v.y += bp[col + 1];
                    *(float2*)(outp + (size_t)row * 384 + col) = v;
                }
            }
        }
    }
}

// ---------------------------------------------------------------------------
// Attention v4: normalization folded into PV (one fewer sync + sS pass).
// ---------------------------------------------------------------------------
#define QP 36
#define SP 50

__global__ void __launch_bounds__(256) attn_kernel(const float* __restrict__ mask,
                                                   const float* __restrict__ logit_scale)
{
    __shared__ float sq[49 * QP];
    __shared__ float sk[49 * QP];
    __shared__ float sv[49 * QP];
    __shared__ float sS[49 * SP];
    __shared__ float sredA[245];
    __shared__ float sredB[245];
    int bh = blockIdx.x;
    int b = bh / 12, h = bh - b * 12;
    int tid = threadIdx.x;

    size_t base = (size_t)bh * 49 * 32;
    const float4* gq4 = (const float4*)(g_q + base);
    const float4* gk4 = (const float4*)(g_k + base);
    for (int u = tid; u < 784; u += 256) {
        if (u < 392) {
            int r = u >> 3, c4 = (u & 7) * 4;
            *(float4*)(sq + r * QP + c4) = gq4[u];
        } else {
            int w = u - 392;
            int r = w >> 3, c4 = (w & 7) * 4;
            *(float4*)(sk + r * QP + c4) = gk4[w];
        }
    }
    if (tid < 196) {
        int r = tid >> 2, c8 = (tid & 3) * 8;
        uint4 pv = *(const uint4*)(g_vh + base + r * 32 + c8);
        float2 f0 = __half22float2(*(__half2*)&pv.x);
        float2 f1 = __half22float2(*(__half2*)&pv.y);
        float2 f2 = __half22float2(*(__half2*)&pv.z);
        float2 f3 = __half22float2(*(__half2*)&pv.w);
        float* d = sv + r * QP + c8;
        d[0] = f0.x; d[1] = f0.y; d[2] = f1.x; d[3] = f1.y;
        d[4] = f2.x; d[5] = f2.y; d[6] = f3.x; d[7] = f3.y;
    }
    __syncthreads();

    if (tid < 98) {
        int r = (tid < 49) ? tid : tid - 49;
        float* s = (tid < 49) ? sq : sk;
        float ss = 0.f;
        #pragma unroll
        for (int d = 0; d < 32; d++) { float x = s[r * QP + d]; ss = fmaf(x, x, ss); }
        float inv = 1.f / fmaxf(sqrtf(ss), 1e-12f);
        if (tid < 49) inv *= expf(fminf(logit_scale[h], 4.60517018598809136804f));
        #pragma unroll
        for (int d = 0; d < 32; d++) s[r * QP + d] *= inv;
    }
    __syncthreads();

    // S = qn @ kn^T : 245 threads, 1 row x <=10 cols
    int si = tid / 5, sp = tid - si * 5;
    int j0 = sp * 10, j1 = min(j0 + 10, 49);
    if (tid < 245) {
        float4 qr[8];
        #pragma unroll
        for (int u = 0; u < 8; u++) qr[u] = *(const float4*)(sq + si * QP + u * 4);
        for (int j = j0; j < j1; j++) {
            float a0 = 0.f;
            #pragma unroll
            for (int u = 0; u < 8; u++) {
                float4 kv = *(const float4*)(sk + j * QP + u * 4);
                a0 = fmaf(qr[u].x, kv.x, a0); a0 = fmaf(qr[u].y, kv.y, a0);
                a0 = fmaf(qr[u].z, kv.z, a0); a0 = fmaf(qr[u].w, kv.w, a0);
            }
            sS[si * SP + j] = a0;
        }
    }
    __syncthreads();

    // softmax pass 1: add rpb+mask, local max
    if (tid < 245) {
        const float* rp = g_rpb + (h * 49 + si) * 49;
        const float* mp = mask + ((size_t)(b & 63) * 49 + si) * 49;
        float lmax = -1e30f;
        for (int j = j0; j < j1; j++) {
            float s = sS[si * SP + j] + rp[j] + mp[j];
            sS[si * SP + j] = s;
            lmax = fmaxf(lmax, s);
        }
        sredA[tid] = lmax;
    }
    __syncthreads();
    // softmax pass 2: exp, local sums (no normalization pass — folded into PV)
    if (tid < 245) {
        float mx = sredA[si * 5];
        #pragma unroll
        for (int p = 1; p < 5; p++) mx = fmaxf(mx, sredA[si * 5 + p]);
        float lsum = 0.f;
        for (int j = j0; j < j1; j++) {
            float e = expf(sS[si * SP + j] - mx);
            sS[si * SP + j] = e;
            lsum += e;
        }
        sredB[tid] = lsum;
    }
    __syncthreads();

    // PV: 200 threads, 2 rows x 4 cols; normalize at the end via row sums.
    if (tid < 200) {
        int ipart = tid >> 3, dq = tid & 7;
        int r0 = ipart * 2;
        bool has1 = (r0 + 1 < 49);
        float sum0 = sredB[r0 * 5] + sredB[r0 * 5 + 1] + sredB[r0 * 5 + 2]
                   + sredB[r0 * 5 + 3] + sredB[r0 * 5 + 4];
        float inv0 = 1.f / sum0;
        float inv1 = 0.f;
        if (has1) {
            float sum1 = sredB[(r0+1) * 5] + sredB[(r0+1) * 5 + 1] + sredB[(r0+1) * 5 + 2]
                       + sredB[(r0+1) * 5 + 3] + sredB[(r0+1) * 5 + 4];
            inv1 = 1.f / sum1;
        }
        float4 a0 = {0, 0, 0, 0}, a1 = {0, 0, 0, 0};
        for (int j = 0; j < 49; j++) {
            float4 v = *(const float4*)(sv + j * QP + dq * 4);
            float s0 = sS[r0 * SP + j];
            a0.x = fmaf(s0, v.x, a0.x); a0.y = fmaf(s0, v.y, a0.y);
            a0.z = fmaf(s0, v.z, a0.z); a0.w = fmaf(s0, v.w, a0.w);
            if (has1) {
                float s1 = sS[(r0 + 1) * SP + j];
                a1.x = fmaf(s1, v.x, a1.x); a1.y = fmaf(s1, v.y, a1.y);
                a1.z = fmaf(s1, v.z, a1.z); a1.w = fmaf(s1, v.w, a1.w);
            }
        }
        size_t o0 = ((size_t)b * 49 + r0) * 384 + h * 32 + dq * 4;
        *(__half2*)(g_oh + o0)     = __half2{__float2half_rn(a0.x * inv0),
                                             __float2half_rn(a0.y * inv0)};
        *(__half2*)(g_oh + o0 + 2) = __half2{__float2half_rn(a0.z * inv0),
                                             __float2half_rn(a0.w * inv0)};
        if (has1) {
            size_t o1 = o0 + 384;
            *(__half2*)(g_oh + o1)     = __half2{__float2half_rn(a1.x * inv1),
                                                 __float2half_rn(a1.y * inv1)};
            *(__half2*)(g_oh + o1 + 2) = __half2{__float2half_rn(a1.z * inv1),
                                                 __float2half_rn(a1.w * inv1)};
        }
    }
}

// ---------------------------------------------------------------------------
extern "C" void kernel_launch(void* const* d_in, const int* in_sizes, int n_in,
                              void* d_out, int out_size) {
    const float* x           = (const float*)d_in[0];
    const float* mask        = (const float*)d_in[1];
    const float* qkv_w       = (const float*)d_in[2];
    const float* q_bias      = (const float*)d_in[3];
    const float* v_bias      = (const float*)d_in[4];
    const float* logit_scale = (const float*)d_in[5];
    const float* cpb_w1      = (const float*)d_in[6];
    const float* cpb_b1      = (const float*)d_in[7];
    const float* cpb_w2      = (const float*)d_in[8];
    const float* proj_w      = (const float*)d_in[9];
    const float* proj_b      = (const float*)d_in[10];
    const float* table       = (const float*)d_in[11];
    const int*   idx         = (const int*)d_in[12];
    float* out = (float*)d_out;

    cudaFuncSetAttribute(gemm_mma<3>, cudaFuncAttributeMaxDynamicSharedMemorySize, GEMM_SMEM3);
    cudaFuncSetAttribute(gemm_mma<1>, cudaFuncAttributeMaxDynamicSharedMemorySize, GEMM_SMEM1);

    __half *xh, *xl, *wh, *wl, *ph, *oh;
    cudaGetSymbolAddress((void**)&xh, g_xh);
    cudaGetSymbolAddress((void**)&xl, g_xl);
    cudaGetSymbolAddress((void**)&wh, g_wh);
    cudaGetSymbolAddress((void**)&wl, g_wl);
    cudaGetSymbolAddress((void**)&ph, g_ph);
    cudaGetSymbolAddress((void**)&oh, g_oh);

    splith_kernel<<<(2048*49*384/8 + 255)/256, 256>>>(x, xh, xl, 2048*49*384/8);
    splith_kernel<<<(1152*384/8 + 255)/256, 256>>>(qkv_w, wh, wl, 1152*384/8);
    splith_kernel<<<(384*384/8 + 255)/256, 256>>>(proj_w, ph, nullptr, 384*384/8);

    cpb_kernel<<<169, 512>>>(table, cpb_w1, cpb_b1, cpb_w2);
    gather_kernel<<<(12 * 2401 + 255) / 256, 256>>>(idx);

    // QKV: q,k columns (n 0..767) 3-term; v columns (n 768..1151) 1-term (fp16 out)
    gemm_mma<3><<<dim3(784, 6), 512, GEMM_SMEM3>>>(xh, xl, wh, wl, 0, 0,
                                                   q_bias, v_bias, nullptr, nullptr);
    gemm_mma<1><<<dim3(784, 3), 512, GEMM_SMEM1>>>(xh, nullptr, wh, nullptr, 0, 768,
                                                   q_bias, v_bias, nullptr, nullptr);
    attn_kernel<<<2048 * 12, 256>>>(mask, logit_scale);
    gemm_mma<1><<<dim3(784, 3), 512, GEMM_SMEM1>>>(oh, nullptr, ph, nullptr, 1, 0,
                                                   nullptr, nullptr, proj_b, out);
}

// round 16
// speedup vs baseline: 1.0977x; 1.0167x over previous
#include <cuda_runtime.h>
#include <cuda_fp16.h>
#include <math.h>
#include <stdint.h>

// B=2048 windows, N=49, C=384, H=12, hd=32, nW=64
__device__ float  g_q [2048u*12*49*32];
__device__ float  g_k [2048u*12*49*32];
__device__ __half g_vh[2048u*12*49*32];  // v in fp16
__device__ __half g_oh[2048u*49*384];    // attn out (fp16), [B][N][C]
__device__ __half g_xh[2048u*49*384];
__device__ __half g_xl[2048u*49*384];    // x residual, x2048
__device__ __half g_wh[1152*384];
__device__ __half g_wl[1152*384];        // w residual, x2048
__device__ __half g_ph[384*384];
__device__ float  g_bt [169*12];
__device__ float  g_rpb[12*49*49];

#define LO_SCALE 2048.f
#define LO_INV   (1.f / 2048.f)

// ---------------------------------------------------------------------------
__device__ __forceinline__ uint32_t smem_u32(const void* p) {
    uint32_t a;
    asm("{ .reg .u64 t; cvta.to.shared.u64 t, %1; cvt.u32.u64 %0, t; }" : "=r"(a) : "l"(p));
    return a;
}
__device__ __forceinline__ void cp_async16(uint32_t dst, const void* src) {
    asm volatile("cp.async.cg.shared.global [%0], [%1], 16;" :: "r"(dst), "l"(src));
}
#define CP_COMMIT() asm volatile("cp.async.commit_group;" ::: "memory")
template<int N> __device__ __forceinline__ void cp_wait() {
    asm volatile("cp.async.wait_group %0;" :: "n"(N) : "memory");
}
__device__ __forceinline__ void ldsm4(uint32_t& r0, uint32_t& r1, uint32_t& r2, uint32_t& r3,
                                      uint32_t addr) {
    asm volatile("ldmatrix.sync.aligned.m8n8.x4.shared.b16 {%0,%1,%2,%3}, [%4];"
                 : "=r"(r0), "=r"(r1), "=r"(r2), "=r"(r3) : "r"(addr));
}
__device__ __forceinline__ void mma_f16(float& c0, float& c1, float& c2, float& c3,
                                        uint32_t a0, uint32_t a1, uint32_t a2, uint32_t a3,
                                        uint32_t b0, uint32_t b1) {
    asm volatile("mma.sync.aligned.m16n8k16.row.col.f32.f16.f16.f32 "
                 "{%0,%1,%2,%3}, {%4,%5,%6,%7}, {%8,%9}, {%0,%1,%2,%3};"
                 : "+f"(c0), "+f"(c1), "+f"(c2), "+f"(c3)
                 : "r"(a0), "r"(a1), "r"(a2), "r"(a3), "r"(b0), "r"(b1));
}

// ---------------------------------------------------------------------------
// Prep: blocks [0,169) do CPB MLP; remaining blocks do the hi/lo splits.
// x: 9408 blocks, qkv_w: 108, proj_w(hi only): 36. 512 threads everywhere.
// ---------------------------------------------------------------------------
#define XB 9408
#define WB 108
#define PB 36

__device__ __forceinline__ void split8(const float* __restrict__ in,
                                       __half* __restrict__ hi, __half* __restrict__ lo,
                                       int i) {
    float4 v0 = ((const float4*)in)[2 * i];
    float4 v1 = ((const float4*)in)[2 * i + 1];
    float vv[8] = {v0.x, v0.y, v0.z, v0.w, v1.x, v1.y, v1.z, v1.w};
    __half h[8], l[8];
    #pragma unroll
    for (int j = 0; j < 8; j++) {
        h[j] = __float2half_rn(vv[j]);
        if (lo) l[j] = __float2half_rn((vv[j] - __half2float(h[j])) * LO_SCALE);
    }
    uint4 hp;
    ((__half2*)&hp)[0] = __half2{h[0], h[1]};
    ((__half2*)&hp)[1] = __half2{h[2], h[3]};
    ((__half2*)&hp)[2] = __half2{h[4], h[5]};
    ((__half2*)&hp)[3] = __half2{h[6], h[7]};
    ((uint4*)hi)[i] = hp;
    if (lo) {
        uint4 lp;
        ((__half2*)&lp)[0] = __half2{l[0], l[1]};
        ((__half2*)&lp)[1] = __half2{l[2], l[3]};
        ((__half2*)&lp)[2] = __half2{l[4], l[5]};
        ((__half2*)&lp)[3] = __half2{l[6], l[7]};
        ((uint4*)lo)[i] = lp;
    }
}

__global__ void __launch_bounds__(512) prep_kernel(
    const float* __restrict__ table, const float* __restrict__ w1,
    const float* __restrict__ b1, const float* __restrict__ w2,
    const float* __restrict__ x, const float* __restrict__ qkv_w,
    const float* __restrict__ proj_w)
{
    __shared__ float red[16];
    int blk = blockIdx.x;
    int j = threadIdx.x;
    if (blk < 169) {
        int t = blk;
        float t0 = table[t * 2 + 0], t1 = table[t * 2 + 1];
        float h = fmaxf(fmaf(t0, w1[j * 2 + 0], fmaf(t1, w1[j * 2 + 1], b1[j])), 0.f);
        for (int hh = 0; hh < 12; hh++) {
            float v = h * w2[hh * 512 + j];
            #pragma unroll
            for (int o = 16; o > 0; o >>= 1) v += __shfl_down_sync(0xffffffffu, v, o);
            if ((j & 31) == 0) red[j >> 5] = v;
            __syncthreads();
            if (j == 0) {
                float s = 0.f;
                #pragma unroll
                for (int w = 0; w < 16; w++) s += red[w];
                g_bt[t * 12 + hh] = 16.f / (1.f + expf(-s));
            }
            __syncthreads();
        }
        return;
    }
    blk -= 169;
    if (blk < XB) {
        split8(x, g_xh, g_xl, blk * 512 + j);
    } else if (blk < XB + WB) {
        split8(qkv_w, g_wh, g_wl, (blk - XB) * 512 + j);
    } else {
        split8(proj_w, g_ph, nullptr, (blk - XB - WB) * 512 + j);
    }
}

__global__ void gather_kernel(const int* __restrict__ idx) {
    int e = blockIdx.x * 256 + threadIdx.x;
    if (e >= 12 * 49 * 49) return;
    int h = e / 2401, ij = e - h * 2401;
    g_rpb[e] = g_bt[idx[ij] * 12 + h];
}

// ---------------------------------------------------------------------------
// fp16-limb warp-MMA GEMM, K-chunk 64, 3-stage single-sync cp.async pipeline.
// (round-13 configuration — best known; unchanged)
// ---------------------------------------------------------------------------
#define PITCHE 72
#define COMP_B (128 * PITCHE * 2)
#define GEMM_SMEM3 (3 * 4 * COMP_B)
#define GEMM_SMEM1 (3 * 2 * COMP_B)

template<int TERMS>
__global__ void __launch_bounds__(512) gemm_mma(
    const __half* __restrict__ Ahi, const __half* __restrict__ Alo,
    const __half* __restrict__ Bhi, const __half* __restrict__ Blo,
    int mode, int n_base,
    const float* __restrict__ bq, const float* __restrict__ bv,
    const float* __restrict__ bp, float* __restrict__ outp)
{
    constexpr int NCOMP = (TERMS == 3) ? 4 : 2;
    constexpr int C_AHI = 0;
    constexpr int C_ALO = 1;
    constexpr int C_BHI = (TERMS == 3) ? 2 : 1;
    constexpr int C_BLO = 3;
    constexpr uint32_t STAGE_B = NCOMP * COMP_B;

    extern __shared__ char sm[];
    uint32_t sbase = smem_u32(sm);
    int tid = threadIdx.x, wid = tid >> 5, lane = tid & 31;
    int g = lane >> 2, t = lane & 3;
    int grp = lane >> 3, rin = lane & 7;
    int m0 = blockIdx.x * 128, n0 = n_base + blockIdx.y * 128;
    int wm = (wid >> 2) * 32, wn = (wid & 3) * 32;

    float cm[2][4][4], cx[2][4][4];
    #pragma unroll
    for (int mi = 0; mi < 2; mi++)
        #pragma unroll
        for (int nj = 0; nj < 4; nj++)
            #pragma unroll
            for (int r = 0; r < 4; r++) { cm[mi][nj][r] = 0.f; cx[mi][nj][r] = 0.f; }

    uint32_t abyte[2], bbyte[2];
    #pragma unroll
    for (int mi = 0; mi < 2; mi++)
        abyte[mi] = (uint32_t)((wm + 16 * mi + (grp & 1) * 8 + rin) * (PITCHE * 2)
                               + (grp >> 1) * 16);
    #pragma unroll
    for (int j = 0; j < 2; j++)
        bbyte[j] = (uint32_t)((wn + 16 * j + (grp >> 1) * 8 + rin) * (PITCHE * 2)
                              + (grp & 1) * 16);

    auto load_stage = [&](int it, int s) {
        int k0 = it * 64;
        uint32_t sb = sbase + (uint32_t)s * STAGE_B;
        #pragma unroll
        for (int q = 0; q < 2; q++) {
            int cc = q * 512 + tid;
            int r = cc >> 3, seg = cc & 7;
            uint32_t off = (uint32_t)(r * (PITCHE * 2) + seg * 16);
            size_t ga = (size_t)(m0 + r) * 384 + k0 + seg * 8;
            size_t gb = (size_t)(n0 + r) * 384 + k0 + seg * 8;
            cp_async16(sb + C_AHI * COMP_B + off, Ahi + ga);
            cp_async16(sb + C_BHI * COMP_B + off, Bhi + gb);
            if (TERMS == 3) {
                cp_async16(sb + C_ALO * COMP_B + off, Alo + ga);
                cp_async16(sb + C_BLO * COMP_B + off, Blo + gb);
            }
        }
        CP_COMMIT();
    };

    load_stage(0, 0);
    load_stage(1, 1);

    for (int it = 0; it < 6; ++it) {
        int s = it % 3;
        if (it < 5) cp_wait<1>(); else cp_wait<0>();
        __syncthreads();
        if (it + 2 < 6) load_stage(it + 2, (it + 2) % 3);
        uint32_t sb = sbase + (uint32_t)s * STAGE_B;
        #pragma unroll
        for (int kc = 0; kc < 4; kc++) {
            uint32_t kb = (uint32_t)(kc * 32);
            uint32_t ah[2][4], al[2][4], bh[2][4], bl[2][4];
            #pragma unroll
            for (int mi = 0; mi < 2; mi++) {
                uint32_t ao = sb + abyte[mi] + kb;
                ldsm4(ah[mi][0], ah[mi][1], ah[mi][2], ah[mi][3], ao + C_AHI * COMP_B);
                if (TERMS == 3)
                    ldsm4(al[mi][0], al[mi][1], al[mi][2], al[mi][3], ao + C_ALO * COMP_B);
            }
            #pragma unroll
            for (int j = 0; j < 2; j++) {
                uint32_t bo = sb + bbyte[j] + kb;
                ldsm4(bh[j][0], bh[j][1], bh[j][2], bh[j][3], bo + C_BHI * COMP_B);
                if (TERMS == 3)
                    ldsm4(bl[j][0], bl[j][1], bl[j][2], bl[j][3], bo + C_BLO * COMP_B);
            }
            #pragma unroll
            for (int mi = 0; mi < 2; mi++)
                #pragma unroll
                for (int nj = 0; nj < 4; nj++) {
                    int j = nj >> 1, hf = (nj & 1) * 2;
                    mma_f16(cm[mi][nj][0], cm[mi][nj][1], cm[mi][nj][2], cm[mi][nj][3],
                            ah[mi][0], ah[mi][1], ah[mi][2], ah[mi][3],
                            bh[j][hf], bh[j][hf + 1]);
                }
            if (TERMS == 3) {
                #pragma unroll
                for (int mi = 0; mi < 2; mi++)
                    #pragma unroll
                    for (int nj = 0; nj < 4; nj++) {
                        int j = nj >> 1, hf = (nj & 1) * 2;
                        mma_f16(cx[mi][nj][0], cx[mi][nj][1], cx[mi][nj][2], cx[mi][nj][3],
                                al[mi][0], al[mi][1], al[mi][2], al[mi][3],
                                bh[j][hf], bh[j][hf + 1]);
                    }
                #pragma unroll
                for (int mi = 0; mi < 2; mi++)
                    #pragma unroll
                    for (int nj = 0; nj < 4; nj++) {
                        int j = nj >> 1, hf = (nj & 1) * 2;
                        mma_f16(cx[mi][nj][0], cx[mi][nj][1], cx[mi][nj][2], cx[mi][nj][3],
                                ah[mi][0], ah[mi][1], ah[mi][2], ah[mi][3],
                                bl[j][hf], bl[j][hf + 1]);
                    }
            }
        }
    }

    #pragma unroll
    for (int mi = 0; mi < 2; mi++) {
        #pragma unroll
        for (int half = 0; half < 2; half++) {
            int row = m0 + wm + 16 * mi + g + 8 * half;
            int b = row / 49, nn = row - b * 49;
            #pragma unroll
            for (int nj = 0; nj < 4; nj++) {
                int col = n0 + wn + 8 * nj + 2 * t;
                float2 v;
                if (TERMS == 3) {
                    v.x = fmaf(cx[mi][nj][2 * half + 0], LO_INV, cm[mi][nj][2 * half + 0]);
                    v.y = fmaf(cx[mi][nj][2 * half + 1], LO_INV, cm[mi][nj][2 * half + 1]);
                } else {
                    v.x = cm[mi][nj][2 * half + 0];
                    v.y = cm[mi][nj][2 * half + 1];
                }
                if (mode == 0) {
                    int which = col / 384;
                    int rem = col - which * 384;
                    int h = rem >> 5, d = rem & 31;
                    if (TERMS == 3) {
                        if (which == 0) { v.x += bq[rem]; v.y += bq[rem + 1]; }
                        float* dst = ((which == 0) ? g_q : g_k)
                                     + (((size_t)b * 12 + h) * 49 + nn) * 32 + d;
                        *(float2*)dst = v;
                    } else {
                        v.x += bv[rem]; v.y += bv[rem + 1];
                        __half* dst = g_vh + (((size_t)b * 12 + h) * 49 + nn) * 32 + d;
                        *(__half2*)dst = __half2{__float2half_rn(v.x), __float2half_rn(v.y)};
                    }
                } else {
                    v.x += bp[col]; v.y += bp[col + 1];
                    *(float2*)(outp + (size_t)row * 384 + col) = v;
                }
            }
        }
    }
}

// ---------------------------------------------------------------------------
// Attention v5: shuffle-parallel normalization (196 thr), folded PV norm.
// ---------------------------------------------------------------------------
#define QP 36
#define SP 50

__global__ void __launch_bounds__(256) attn_kernel(const float* __restrict__ mask,
                                                   const float* __restrict__ logit_scale)
{
    __shared__ float sq[49 * QP];
    __shared__ float sk[49 * QP];
    __shared__ float sv[49 * QP];
    __shared__ float sS[49 * SP];
    __shared__ float sredA[245];
    __shared__ float sredB[245];
    int bh = blockIdx.x;
    int b = bh / 12, h = bh - b * 12;
    int tid = threadIdx.x;

    size_t base = (size_t)bh * 49 * 32;
    const float4* gq4 = (const float4*)(g_q + base);
    const float4* gk4 = (const float4*)(g_k + base);
    for (int u = tid; u < 784; u += 256) {
        if (u < 392) {
            int r = u >> 3, c4 = (u & 7) * 4;
            *(float4*)(sq + r * QP + c4) = gq4[u];
        } else {
            int w = u - 392;
            int r = w >> 3, c4 = (w & 7) * 4;
            *(float4*)(sk + r * QP + c4) = gk4[w];
        }
    }
    if (tid < 196) {
        int r = tid >> 2, c8 = (tid & 3) * 8;
        uint4 pv = *(const uint4*)(g_vh + base + r * 32 + c8);
        float2 f0 = __half22float2(*(__half2*)&pv.x);
        float2 f1 = __half22float2(*(__half2*)&pv.y);
        float2 f2 = __half22float2(*(__half2*)&pv.z);
        float2 f3 = __half22float2(*(__half2*)&pv.w);
        float* d = sv + r * QP + c8;
        d[0] = f0.x; d[1] = f0.y; d[2] = f1.x; d[3] = f1.y;
        d[4] = f2.x; d[5] = f2.y; d[6] = f3.x; d[7] = f3.y;
    }
    __syncthreads();

    // normalize q (with logit scale) and k: 196 threads, 4 lanes per row,
    // shuffle reduction within each lane-quad.
    if (tid < 196) {
        int r = tid >> 2, p = tid & 3;
        unsigned smask = (tid < 192) ? 0xffffffffu : 0x0000000fu;
        float sc = expf(fminf(logit_scale[h], 4.60517018598809136804f));
        #pragma unroll
        for (int which = 0; which < 2; which++) {
            float* s = which ? sk : sq;
            float* row = s + r * QP + p * 8;
            float4 va = *(float4*)(row);
            float4 vb = *(float4*)(row + 4);
            float ss = va.x * va.x;
            ss = fmaf(va.y, va.y, ss); ss = fmaf(va.z, va.z, ss);
            ss = fmaf(va.w, va.w, ss); ss = fmaf(vb.x, vb.x, ss);
            ss = fmaf(vb.y, vb.y, ss); ss = fmaf(vb.z, vb.z, ss);
            ss = fmaf(vb.w, vb.w, ss);
            ss += __shfl_xor_sync(smask, ss, 1);
            ss += __shfl_xor_sync(smask, ss, 2);
            float inv = 1.f / fmaxf(sqrtf(ss), 1e-12f);
            if (which == 0) inv *= sc;
            va.x *= inv; va.y *= inv; va.z *= inv; va.w *= inv;
            vb.x *= inv; vb.y *= inv; vb.z *= inv; vb.w *= inv;
            *(float4*)(row) = va;
            *(float4*)(row + 4) = vb;
        }
    }
    __syncthreads();

    // S = qn @ kn^T : 245 threads, 1 row x <=10 cols
    int si = tid / 5, sp = tid - si * 5;
    int j0 = sp * 10, j1 = min(j0 + 10, 49);
    if (tid < 245) {
        float4 qr[8];
        #pragma unroll
        for (int u = 0; u < 8; u++) qr[u] = *(const float4*)(sq + si * QP + u * 4);
        for (int j = j0; j < j1; j++) {
            float a0 = 0.f;
            #pragma unroll
            for (int u = 0; u < 8; u++) {
                float4 kv = *(const float4*)(sk + j * QP + u * 4);
                a0 = fmaf(qr[u].x, kv.x, a0); a0 = fmaf(qr[u].y, kv.y, a0);
                a0 = fmaf(qr[u].z, kv.z, a0); a0 = fmaf(qr[u].w, kv.w, a0);
            }
            sS[si * SP + j] = a0;
        }
    }
    __syncthreads();

    // softmax pass 1: add rpb+mask, local max
    if (tid < 245) {
        const float* rp = g_rpb + (h * 49 + si) * 49;
        const float* mp = mask + ((size_t)(b & 63) * 49 + si) * 49;
        float lmax = -1e30f;
        for (int j = j0; j < j1; j++) {
            float s = sS[si * SP + j] + rp[j] + mp[j];
            sS[si * SP + j] = s;
            lmax = fmaxf(lmax, s);
        }
        sredA[tid] = lmax;
    }
    __syncthreads();
    // softmax pass 2: exp + local sums (normalization folded into PV)
    if (tid < 245) {
        float mx = sredA[si * 5];
        #pragma unroll
        for (int p = 1; p < 5; p++) mx = fmaxf(mx, sredA[si * 5 + p]);
        float lsum = 0.f;
        for (int j = j0; j < j1; j++) {
            float e = expf(sS[si * SP + j] - mx);
            sS[si * SP + j] = e;
            lsum += e;
        }
        sredB[tid] = lsum;
    }
    __syncthreads();

    // PV: 200 threads, 2 rows x 4 cols; normalize at the end via row sums.
    if (tid < 200) {
        int ipart = tid >> 3, dq = tid & 7;
        int r0 = ipart * 2;
        bool has1 = (r0 + 1 < 49);
        float sum0 = sredB[r0 * 5] + sredB[r0 * 5 + 1] + sredB[r0 * 5 + 2]
                   + sredB[r0 * 5 + 3] + sredB[r0 * 5 + 4];
        float inv0 = 1.f / sum0;
        float inv1 = 0.f;
        if (has1) {
            float sum1 = sredB[(r0+1) * 5] + sredB[(r0+1) * 5 + 1] + sredB[(r0+1) * 5 + 2]
                       + sredB[(r0+1) * 5 + 3] + sredB[(r0+1) * 5 + 4];
            inv1 = 1.f / sum1;
        }
        float4 a0 = {0, 0, 0, 0}, a1 = {0, 0, 0, 0};
        for (int j = 0; j < 49; j++) {
            float4 v = *(const float4*)(sv + j * QP + dq * 4);
            float s0 = sS[r0 * SP + j];
            a0.x = fmaf(s0, v.x, a0.x); a0.y = fmaf(s0, v.y, a0.y);
            a0.z = fmaf(s0, v.z, a0.z); a0.w = fmaf(s0, v.w, a0.w);
            if (has1) {
                float s1 = sS[(r0 + 1) * SP + j];
                a1.x = fmaf(s1, v.x, a1.x); a1.y = fmaf(s1, v.y, a1.y);
                a1.z = fmaf(s1, v.z, a1.z); a1.w = fmaf(s1, v.w, a1.w);
            }
        }
        size_t o0 = ((size_t)b * 49 + r0) * 384 + h * 32 + dq * 4;
        *(__half2*)(g_oh + o0)     = __half2{__float2half_rn(a0.x * inv0),
                                             __float2half_rn(a0.y * inv0)};
        *(__half2*)(g_oh + o0 + 2) = __half2{__float2half_rn(a0.z * inv0),
                                             __float2half_rn(a0.w * inv0)};
        if (has1) {
            size_t o1 = o0 + 384;
            *(__half2*)(g_oh + o1)     = __half2{__float2half_rn(a1.x * inv1),
                                                 __float2half_rn(a1.y * inv1)};
            *(__half2*)(g_oh + o1 + 2) = __half2{__float2half_rn(a1.z * inv1),
                                                 __float2half_rn(a1.w * inv1)};
        }
    }
}

// ---------------------------------------------------------------------------
extern "C" void kernel_launch(void* const* d_in, const int* in_sizes, int n_in,
                              void* d_out, int out_size) {
    const float* x           = (const float*)d_in[0];
    const float* mask        = (const float*)d_in[1];
    const float* qkv_w       = (const float*)d_in[2];
    const float* q_bias      = (const float*)d_in[3];
    const float* v_bias      = (const float*)d_in[4];
    const float* logit_scale = (const float*)d_in[5];
    const float* cpb_w1      = (const float*)d_in[6];
    const float* cpb_b1      = (const float*)d_in[7];
    const float* cpb_w2      = (const float*)d_in[8];
    const float* proj_w      = (const float*)d_in[9];
    const float* proj_b      = (const float*)d_in[10];
    const float* table       = (const float*)d_in[11];
    const int*   idx         = (const int*)d_in[12];
    float* out = (float*)d_out;

    cudaFuncSetAttribute(gemm_mma<3>, cudaFuncAttributeMaxDynamicSharedMemorySize, GEMM_SMEM3);
    cudaFuncSetAttribute(gemm_mma<1>, cudaFuncAttributeMaxDynamicSharedMemorySize, GEMM_SMEM1);

    __half *xh, *xl, *wh, *wl, *ph, *oh;
    cudaGetSymbolAddress((void**)&xh, g_xh);
    cudaGetSymbolAddress((void**)&xl, g_xl);
    cudaGetSymbolAddress((void**)&wh, g_wh);
    cudaGetSymbolAddress((void**)&wl, g_wl);
    cudaGetSymbolAddress((void**)&ph, g_ph);
    cudaGetSymbolAddress((void**)&oh, g_oh);

    // cpb + all splits, concurrent in one launch
    prep_kernel<<<169 + XB + WB + PB, 512>>>(table, cpb_w1, cpb_b1, cpb_w2,
                                             x, qkv_w, proj_w);
    gather_kernel<<<(12 * 2401 + 255) / 256, 256>>>(idx);

    // QKV: q,k columns (n 0..767) 3-term; v columns (n 768..1151) 1-term (fp16 out)
    gemm_mma<3><<<dim3(784, 6), 512, GEMM_SMEM3>>>(xh, xl, wh, wl, 0, 0,
                                                   q_bias, v_bias, nullptr, nullptr);
    gemm_mma<1><<<dim3(784, 3), 512, GEMM_SMEM1>>>(xh, nullptr, wh, nullptr, 0, 768,
                                                   q_bias, v_bias, nullptr, nullptr);
    attn_kernel<<<2048 * 12, 256>>>(mask, logit_scale);
    gemm_mma<1><<<dim3(784, 3), 512, GEMM_SMEM1>>>(oh, nullptr, ph, nullptr, 1, 0,
                                                   nullptr, nullptr, proj_b, out);
}

// round 17
// speedup vs baseline: 1.1272x; 1.0268x over previous
#include <cuda_runtime.h>
#include <cuda_fp16.h>
#include <math.h>
#include <stdint.h>

// B=2048 windows, N=49, C=384, H=12, hd=32, nW=64
__device__ float  g_q [2048u*12*49*32];
__device__ float  g_k [2048u*12*49*32];
__device__ __half g_vh[2048u*12*49*32];  // v in fp16
__device__ __half g_oh[2048u*49*384];    // attn out (fp16), [B][N][C]
__device__ __half g_xh[2048u*49*384];
__device__ __half g_xl[2048u*49*384];    // x residual, x2048
__device__ __half g_wh[1152*384];
__device__ __half g_wl[1152*384];        // w residual, x2048
__device__ __half g_ph[384*384];
__device__ float  g_bt [169*12];
__device__ float  g_rpb[12*49*49];

#define LO_SCALE 2048.f
#define LO_INV   (1.f / 2048.f)

// ---------------------------------------------------------------------------
__device__ __forceinline__ uint32_t smem_u32(const void* p) {
    uint32_t a;
    asm("{ .reg .u64 t; cvta.to.shared.u64 t, %1; cvt.u32.u64 %0, t; }" : "=r"(a) : "l"(p));
    return a;
}
__device__ __forceinline__ void cp_async16(uint32_t dst, const void* src) {
    asm volatile("cp.async.cg.shared.global [%0], [%1], 16;" :: "r"(dst), "l"(src));
}
#define CP_COMMIT() asm volatile("cp.async.commit_group;" ::: "memory")
template<int N> __device__ __forceinline__ void cp_wait() {
    asm volatile("cp.async.wait_group %0;" :: "n"(N) : "memory");
}
__device__ __forceinline__ void ldsm4(uint32_t& r0, uint32_t& r1, uint32_t& r2, uint32_t& r3,
                                      uint32_t addr) {
    asm volatile("ldmatrix.sync.aligned.m8n8.x4.shared.b16 {%0,%1,%2,%3}, [%4];"
                 : "=r"(r0), "=r"(r1), "=r"(r2), "=r"(r3) : "r"(addr));
}
__device__ __forceinline__ void mma_f16(float& c0, float& c1, float& c2, float& c3,
                                        uint32_t a0, uint32_t a1, uint32_t a2, uint32_t a3,
                                        uint32_t b0, uint32_t b1) {
    asm volatile("mma.sync.aligned.m16n8k16.row.col.f32.f16.f16.f32 "
                 "{%0,%1,%2,%3}, {%4,%5,%6,%7}, {%8,%9}, {%0,%1,%2,%3};"
                 : "+f"(c0), "+f"(c1), "+f"(c2), "+f"(c3)
                 : "r"(a0), "r"(a1), "r"(a2), "r"(a3), "r"(b0), "r"(b1));
}

// ---------------------------------------------------------------------------
// Prep: blocks [0,169) do CPB MLP; remaining blocks do the hi/lo splits.
// ---------------------------------------------------------------------------
#define XB 9408
#define WB 108
#define PB 36

__device__ __forceinline__ void split8(const float* __restrict__ in,
                                       __half* __restrict__ hi, __half* __restrict__ lo,
                                       int i) {
    float4 v0 = ((const float4*)in)[2 * i];
    float4 v1 = ((const float4*)in)[2 * i + 1];
    float vv[8] = {v0.x, v0.y, v0.z, v0.w, v1.x, v1.y, v1.z, v1.w};
    __half h[8], l[8];
    #pragma unroll
    for (int j = 0; j < 8; j++) {
        h[j] = __float2half_rn(vv[j]);
        if (lo) l[j] = __float2half_rn((vv[j] - __half2float(h[j])) * LO_SCALE);
    }
    uint4 hp;
    ((__half2*)&hp)[0] = __half2{h[0], h[1]};
    ((__half2*)&hp)[1] = __half2{h[2], h[3]};
    ((__half2*)&hp)[2] = __half2{h[4], h[5]};
    ((__half2*)&hp)[3] = __half2{h[6], h[7]};
    ((uint4*)hi)[i] = hp;
    if (lo) {
        uint4 lp;
        ((__half2*)&lp)[0] = __half2{l[0], l[1]};
        ((__half2*)&lp)[1] = __half2{l[2], l[3]};
        ((__half2*)&lp)[2] = __half2{l[4], l[5]};
        ((__half2*)&lp)[3] = __half2{l[6], l[7]};
        ((uint4*)lo)[i] = lp;
    }
}

__global__ void __launch_bounds__(512) prep_kernel(
    const float* __restrict__ table, const float* __restrict__ w1,
    const float* __restrict__ b1, const float* __restrict__ w2,
    const float* __restrict__ x, const float* __restrict__ qkv_w,
    const float* __restrict__ proj_w)
{
    __shared__ float red[16];
    int blk = blockIdx.x;
    int j = threadIdx.x;
    if (blk < 169) {
        int t = blk;
        float t0 = table[t * 2 + 0], t1 = table[t * 2 + 1];
        float h = fmaxf(fmaf(t0, w1[j * 2 + 0], fmaf(t1, w1[j * 2 + 1], b1[j])), 0.f);
        for (int hh = 0; hh < 12; hh++) {
            float v = h * w2[hh * 512 + j];
            #pragma unroll
            for (int o = 16; o > 0; o >>= 1) v += __shfl_down_sync(0xffffffffu, v, o);
            if ((j & 31) == 0) red[j >> 5] = v;
            __syncthreads();
            if (j == 0) {
                float s = 0.f;
                #pragma unroll
                for (int w = 0; w < 16; w++) s += red[w];
                g_bt[t * 12 + hh] = 16.f / (1.f + expf(-s));
            }
            __syncthreads();
        }
        return;
    }
    blk -= 169;
    if (blk < XB) {
        split8(x, g_xh, g_xl, blk * 512 + j);
    } else if (blk < XB + WB) {
        split8(qkv_w, g_wh, g_wl, (blk - XB) * 512 + j);
    } else {
        split8(proj_w, g_ph, nullptr, (blk - XB - WB) * 512 + j);
    }
}

__global__ void gather_kernel(const int* __restrict__ idx) {
    int e = blockIdx.x * 256 + threadIdx.x;
    if (e >= 12 * 49 * 49) return;
    int h = e / 2401, ij = e - h * 2401;
    g_rpb[e] = g_bt[idx[ij] * 12 + h];
}

// ---------------------------------------------------------------------------
// fp16-limb warp-MMA GEMM, K-chunk 64, 3-stage single-sync cp.async pipeline.
// TERMS=3: 1 block/SM (smem-bound). TERMS=1: 2 blocks/SM (reg-capped to 64).
// ---------------------------------------------------------------------------
#define PITCHE 72
#define COMP_B (128 * PITCHE * 2)
#define GEMM_SMEM3 (3 * 4 * COMP_B)
#define GEMM_SMEM1 (3 * 2 * COMP_B)

template<int TERMS>
__global__ void __launch_bounds__(512, (TERMS == 1) ? 2 : 1) gemm_mma(
    const __half* __restrict__ Ahi, const __half* __restrict__ Alo,
    const __half* __restrict__ Bhi, const __half* __restrict__ Blo,
    int mode, int n_base,
    const float* __restrict__ bq, const float* __restrict__ bv,
    const float* __restrict__ bp, float* __restrict__ outp)
{
    constexpr int NCOMP = (TERMS == 3) ? 4 : 2;
    constexpr int C_AHI = 0;
    constexpr int C_ALO = 1;
    constexpr int C_BHI = (TERMS == 3) ? 2 : 1;
    constexpr int C_BLO = 3;
    constexpr uint32_t STAGE_B = NCOMP * COMP_B;

    extern __shared__ char sm[];
    uint32_t sbase = smem_u32(sm);
    int tid = threadIdx.x, wid = tid >> 5, lane = tid & 31;
    int g = lane >> 2, t = lane & 3;
    int grp = lane >> 3, rin = lane & 7;
    int m0 = blockIdx.x * 128, n0 = n_base + blockIdx.y * 128;
    int wm = (wid >> 2) * 32, wn = (wid & 3) * 32;

    float cm[2][4][4], cx[2][4][4];
    #pragma unroll
    for (int mi = 0; mi < 2; mi++)
        #pragma unroll
        for (int nj = 0; nj < 4; nj++)
            #pragma unroll
            for (int r = 0; r < 4; r++) { cm[mi][nj][r] = 0.f; cx[mi][nj][r] = 0.f; }

    uint32_t abyte[2], bbyte[2];
    #pragma unroll
    for (int mi = 0; mi < 2; mi++)
        abyte[mi] = (uint32_t)((wm + 16 * mi + (grp & 1) * 8 + rin) * (PITCHE * 2)
                               + (grp >> 1) * 16);
    #pragma unroll
    for (int j = 0; j < 2; j++)
        bbyte[j] = (uint32_t)((wn + 16 * j + (grp >> 1) * 8 + rin) * (PITCHE * 2)
                              + (grp & 1) * 16);

    auto load_stage = [&](int it, int s) {
        int k0 = it * 64;
        uint32_t sb = sbase + (uint32_t)s * STAGE_B;
        #pragma unroll
        for (int q = 0; q < 2; q++) {
            int cc = q * 512 + tid;
            int r = cc >> 3, seg = cc & 7;
            uint32_t off = (uint32_t)(r * (PITCHE * 2) + seg * 16);
            size_t ga = (size_t)(m0 + r) * 384 + k0 + seg * 8;
            size_t gb = (size_t)(n0 + r) * 384 + k0 + seg * 8;
            cp_async16(sb + C_AHI * COMP_B + off, Ahi + ga);
            cp_async16(sb + C_BHI * COMP_B + off, Bhi + gb);
            if (TERMS == 3) {
                cp_async16(sb + C_ALO * COMP_B + off, Alo + ga);
                cp_async16(sb + C_BLO * COMP_B + off, Blo + gb);
            }
        }
        CP_COMMIT();
    };

    load_stage(0, 0);
    load_stage(1, 1);

    for (int it = 0; it < 6; ++it) {
        int s = it % 3;
        if (it < 5) cp_wait<1>(); else cp_wait<0>();
        __syncthreads();
        if (it + 2 < 6) load_stage(it + 2, (it + 2) % 3);
        uint32_t sb = sbase + (uint32_t)s * STAGE_B;
        #pragma unroll
        for (int kc = 0; kc < 4; kc++) {
            uint32_t kb = (uint32_t)(kc * 32);
            uint32_t ah[2][4], al[2][4], bh[2][4], bl[2][4];
            #pragma unroll
            for (int mi = 0; mi < 2; mi++) {
                uint32_t ao = sb + abyte[mi] + kb;
                ldsm4(ah[mi][0], ah[mi][1], ah[mi][2], ah[mi][3], ao + C_AHI * COMP_B);
                if (TERMS == 3)
                    ldsm4(al[mi][0], al[mi][1], al[mi][2], al[mi][3], ao + C_ALO * COMP_B);
            }
            #pragma unroll
            for (int j = 0; j < 2; j++) {
                uint32_t bo = sb + bbyte[j] + kb;
                ldsm4(bh[j][0], bh[j][1], bh[j][2], bh[j][3], bo + C_BHI * COMP_B);
                if (TERMS == 3)
                    ldsm4(bl[j][0], bl[j][1], bl[j][2], bl[j][3], bo + C_BLO * COMP_B);
            }
            #pragma unroll
            for (int mi = 0; mi < 2; mi++)
                #pragma unroll
                for (int nj = 0; nj < 4; nj++) {
                    int j = nj >> 1, hf = (nj & 1) * 2;
                    mma_f16(cm[mi][nj][0], cm[mi][nj][1], cm[mi][nj][2], cm[mi][nj][3],
                            ah[mi][0], ah[mi][1], ah[mi][2], ah[mi][3],
                            bh[j][hf], bh[j][hf + 1]);
                }
            if (TERMS == 3) {
                #pragma unroll
                for (int mi = 0; mi < 2; mi++)
                    #pragma unroll
                    for (int nj = 0; nj < 4; nj++) {
                        int j = nj >> 1, hf = (nj & 1) * 2;
                        mma_f16(cx[mi][nj][0], cx[mi][nj][1], cx[mi][nj][2], cx[mi][nj][3],
                                al[mi][0], al[mi][1], al[mi][2], al[mi][3],
                                bh[j][hf], bh[j][hf + 1]);
                    }
                #pragma unroll
                for (int mi = 0; mi < 2; mi++)
                    #pragma unroll
                    for (int nj = 0; nj < 4; nj++) {
                        int j = nj >> 1, hf = (nj & 1) * 2;
                        mma_f16(cx[mi][nj][0], cx[mi][nj][1], cx[mi][nj][2], cx[mi][nj][3],
                                ah[mi][0], ah[mi][1], ah[mi][2], ah[mi][3],
                                bl[j][hf], bl[j][hf + 1]);
                    }
            }
        }
    }

    #pragma unroll
    for (int mi = 0; mi < 2; mi++) {
        #pragma unroll
        for (int half = 0; half < 2; half++) {
            int row = m0 + wm + 16 * mi + g + 8 * half;
            int b = row / 49, nn = row - b * 49;
            #pragma unroll
            for (int nj = 0; nj < 4; nj++) {
                int col = n0 + wn + 8 * nj + 2 * t;
                float2 v;
                if (TERMS == 3) {
                    v.x = fmaf(cx[mi][nj][2 * half + 0], LO_INV, cm[mi][nj][2 * half + 0]);
                    v.y = fmaf(cx[mi][nj][2 * half + 1], LO_INV, cm[mi][nj][2 * half + 1]);
                } else {
                    v.x = cm[mi][nj][2 * half + 0];
                    v.y = cm[mi][nj][2 * half + 1];
                }
                if (mode == 0) {
                    int which = col / 384;
                    int rem = col - which * 384;
                    int h = rem >> 5, d = rem & 31;
                    if (TERMS == 3) {
                        if (which == 0) { v.x += bq[rem]; v.y += bq[rem + 1]; }
                        float* dst = ((which == 0) ? g_q : g_k)
                                     + (((size_t)b * 12 + h) * 49 + nn) * 32 + d;
                        *(float2*)dst = v;
                    } else {
                        v.x += bv[rem]; v.y += bv[rem + 1];
                        __half* dst = g_vh + (((size_t)b * 12 + h) * 49 + nn) * 32 + d;
                        *(__half2*)dst = __half2{__float2half_rn(v.x), __float2half_rn(v.y)};
                    }
                } else {
                    v.x += bp[col]; v.y += bp[col + 1];
                    *(float2*)(outp + (size_t)row * 384 + col) = v;
                }
            }
        }
    }
}

// ---------------------------------------------------------------------------
// Attention v5 (round-16): shuffle-parallel normalization, folded PV norm.
// ---------------------------------------------------------------------------
#define QP 36
#define SP 50

__global__ void __launch_bounds__(256) attn_kernel(const float* __restrict__ mask,
                                                   const float* __restrict__ logit_scale)
{
    __shared__ float sq[49 * QP];
    __shared__ float sk[49 * QP];
    __shared__ float sv[49 * QP];
    __shared__ float sS[49 * SP];
    __shared__ float sredA[245];
    __shared__ float sredB[245];
    int bh = blockIdx.x;
    int b = bh / 12, h = bh - b * 12;
    int tid = threadIdx.x;

    size_t base = (size_t)bh * 49 * 32;
    const float4* gq4 = (const float4*)(g_q + base);
    const float4* gk4 = (const float4*)(g_k + base);
    for (int u = tid; u < 784; u += 256) {
        if (u < 392) {
            int r = u >> 3, c4 = (u & 7) * 4;
            *(float4*)(sq + r * QP + c4) = gq4[u];
        } else {
            int w = u - 392;
            int r = w >> 3, c4 = (w & 7) * 4;
            *(float4*)(sk + r * QP + c4) = gk4[w];
        }
    }
    if (tid < 196) {
        int r = tid >> 2, c8 = (tid & 3) * 8;
        uint4 pv = *(const uint4*)(g_vh + base + r * 32 + c8);
        float2 f0 = __half22float2(*(__half2*)&pv.x);
        float2 f1 = __half22float2(*(__half2*)&pv.y);
        float2 f2 = __half22float2(*(__half2*)&pv.z);
        float2 f3 = __half22float2(*(__half2*)&pv.w);
        float* d = sv + r * QP + c8;
        d[0] = f0.x; d[1] = f0.y; d[2] = f1.x; d[3] = f1.y;
        d[4] = f2.x; d[5] = f2.y; d[6] = f3.x; d[7] = f3.y;
    }
    __syncthreads();

    if (tid < 196) {
        int r = tid >> 2, p = tid & 3;
        unsigned smask = (tid < 192) ? 0xffffffffu : 0x0000000fu;
        float sc = expf(fminf(logit_scale[h], 4.60517018598809136804f));
        #pragma unroll
        for (int which = 0; which < 2; which++) {
            float* s = which ? sk : sq;
            float* row = s + r * QP + p * 8;
            float4 va = *(float4*)(row);
            float4 vb = *(float4*)(row + 4);
            float ss = va.x * va.x;
            ss = fmaf(va.y, va.y, ss); ss = fmaf(va.z, va.z, ss);
            ss = fmaf(va.w, va.w, ss); ss = fmaf(vb.x, vb.x, ss);
            ss = fmaf(vb.y, vb.y, ss); ss = fmaf(vb.z, vb.z, ss);
            ss = fmaf(vb.w, vb.w, ss);
            ss += __shfl_xor_sync(smask, ss, 1);
            ss += __shfl_xor_sync(smask, ss, 2);
            float inv = 1.f / fmaxf(sqrtf(ss), 1e-12f);
            if (which == 0) inv *= sc;
            va.x *= inv; va.y *= inv; va.z *= inv; va.w *= inv;
            vb.x *= inv; vb.y *= inv; vb.z *= inv; vb.w *= inv;
            *(float4*)(row) = va;
            *(float4*)(row + 4) = vb;
        }
    }
    __syncthreads();

    int si = tid / 5, sp = tid - si * 5;
    int j0 = sp * 10, j1 = min(j0 + 10, 49);
    if (tid < 245) {
        float4 qr[8];
        #pragma unroll
        for (int u = 0; u < 8; u++) qr[u] = *(const float4*)(sq + si * QP + u * 4);
        for (int j = j0; j < j1; j++) {
            float a0 = 0.f;
            #pragma unroll
            for (int u = 0; u < 8; u++) {
                float4 kv = *(const float4*)(sk + j * QP + u * 4);
                a0 = fmaf(qr[u].x, kv.x, a0); a0 = fmaf(qr[u].y, kv.y, a0);
                a0 = fmaf(qr[u].z, kv.z, a0); a0 = fmaf(qr[u].w, kv.w, a0);
            }
            sS[si * SP + j] = a0;
        }
    }
    __syncthreads();

    if (tid < 245) {
        const float* rp = g_rpb + (h * 49 + si) * 49;
        const float* mp = mask + ((size_t)(b & 63) * 49 + si) * 49;
        float lmax = -1e30f;
        for (int j = j0; j < j1; j++) {
            float s = sS[si * SP + j] + rp[j] + mp[j];
            sS[si * SP + j] = s;
            lmax = fmaxf(lmax, s);
        }
        sredA[tid] = lmax;
    }
    __syncthreads();
    if (tid < 245) {
        float mx = sredA[si * 5];
        #pragma unroll
        for (int p = 1; p < 5; p++) mx = fmaxf(mx, sredA[si * 5 + p]);
        float lsum = 0.f;
        for (int j = j0; j < j1; j++) {
            float e = expf(sS[si * SP + j] - mx);
            sS[si * SP + j] = e;
            lsum += e;
        }
        sredB[tid] = lsum;
    }
    __syncthreads();

    if (tid < 200) {
        int ipart = tid >> 3, dq = tid & 7;
        int r0 = ipart * 2;
        bool has1 = (r0 + 1 < 49);
        float sum0 = sredB[r0 * 5] + sredB[r0 * 5 + 1] + sredB[r0 * 5 + 2]
                   + sredB[r0 * 5 + 3] + sredB[r0 * 5 + 4];
        float inv0 = 1.f / sum0;
        float inv1 = 0.f;
        if (has1) {
            float sum1 = sredB[(r0+1) * 5] + sredB[(r0+1) * 5 + 1] + sredB[(r0+1) * 5 + 2]
                       + sredB[(r0+1) * 5 + 3] + sredB[(r0+1) * 5 + 4];
            inv1 = 1.f / sum1;
        }
        float4 a0 = {0, 0, 0, 0}, a1 = {0, 0, 0, 0};
        for (int j = 0; j < 49; j++) {
            float4 v = *(const float4*)(sv + j * QP + dq * 4);
            float s0 = sS[r0 * SP + j];
            a0.x = fmaf(s0, v.x, a0.x); a0.y = fmaf(s0, v.y, a0.y);
            a0.z = fmaf(s0, v.z, a0.z); a0.w = fmaf(s0, v.w, a0.w);
            if (has1) {
                float s1 = sS[(r0 + 1) * SP + j];
                a1.x = fmaf(s1, v.x, a1.x); a1.y = fmaf(s1, v.y, a1.y);
                a1.z = fmaf(s1, v.z, a1.z); a1.w = fmaf(s1, v.w, a1.w);
            }
        }
        size_t o0 = ((size_t)b * 49 + r0) * 384 + h * 32 + dq * 4;
        *(__half2*)(g_oh + o0)     = __half2{__float2half_rn(a0.x * inv0),
                                             __float2half_rn(a0.y * inv0)};
        *(__half2*)(g_oh + o0 + 2) = __half2{__float2half_rn(a0.z * inv0),
                                             __float2half_rn(a0.w * inv0)};
        if (has1) {
            size_t o1 = o0 + 384;
            *(__half2*)(g_oh + o1)     = __half2{__float2half_rn(a1.x * inv1),
                                                 __float2half_rn(a1.y * inv1)};
            *(__half2*)(g_oh + o1 + 2) = __half2{__float2half_rn(a1.z * inv1),
                                                 __float2half_rn(a1.w * inv1)};
        }
    }
}

// ---------------------------------------------------------------------------
extern "C" void kernel_launch(void* const* d_in, const int* in_sizes, int n_in,
                              void* d_out, int out_size) {
    const float* x           = (const float*)d_in[0];
    const float* mask        = (const float*)d_in[1];
    const float* qkv_w       = (const float*)d_in[2];
    const float* q_bias      = (const float*)d_in[3];
    const float* v_bias      = (const float*)d_in[4];
    const float* logit_scale = (const float*)d_in[5];
    const float* cpb_w1      = (const float*)d_in[6];
    const float* cpb_b1      = (const float*)d_in[7];
    const float* cpb_w2      = (const float*)d_in[8];
    const float* proj_w      = (const float*)d_in[9];
    const float* proj_b      = (const float*)d_in[10];
    const float* table       = (const float*)d_in[11];
    const int*   idx         = (const int*)d_in[12];
    float* out = (float*)d_out;

    cudaFuncSetAttribute(gemm_mma<3>, cudaFuncAttributeMaxDynamicSharedMemorySize, GEMM_SMEM3);
    cudaFuncSetAttribute(gemm_mma<1>, cudaFuncAttributeMaxDynamicSharedMemorySize, GEMM_SMEM1);

    __half *xh, *xl, *wh, *wl, *ph, *oh;
    cudaGetSymbolAddress((void**)&xh, g_xh);
    cudaGetSymbolAddress((void**)&xl, g_xl);
    cudaGetSymbolAddress((void**)&wh, g_wh);
    cudaGetSymbolAddress((void**)&wl, g_wl);
    cudaGetSymbolAddress((void**)&ph, g_ph);
    cudaGetSymbolAddress((void**)&oh, g_oh);

    prep_kernel<<<169 + XB + WB + PB, 512>>>(table, cpb_w1, cpb_b1, cpb_w2,
                                             x, qkv_w, proj_w);
    gather_kernel<<<(12 * 2401 + 255) / 256, 256>>>(idx);

    gemm_mma<3><<<dim3(784, 6), 512, GEMM_SMEM3>>>(xh, xl, wh, wl, 0, 0,
                                                   q_bias, v_bias, nullptr, nullptr);
    gemm_mma<1><<<dim3(784, 3), 512, GEMM_SMEM1>>>(xh, nullptr, wh, nullptr, 0, 768,
                                                   q_bias, v_bias, nullptr, nullptr);
    attn_kernel<<<2048 * 12, 256>>>(mask, logit_scale);
    gemm_mma<1><<<dim3(784, 3), 512, GEMM_SMEM1>>>(oh, nullptr, ph, nullptr, 1, 0,
                                                   nullptr, nullptr, proj_b, out);
}